// round 8
// baseline (speedup 1.0000x reference)
#include <cuda_runtime.h>

// L2LossWithRebalancing — GB300 sm_103a, round 8.
// Latency-bound loss kernel attacked via: PXT=1 (2x warps in flight),
// sentinel-padded candidate slots (unconditional batched loads, no guarded
// serial chain), hoisted pred loads. Build pads multi-cell slots to 8.

#define K_REAL 313
#define GRIDW 256
#define NCELLS (GRIDW * GRIDW)
#define CAPI 8
#define SCAP 64
#define NPIX (16 * 256 * 256)
#define CH_STRIDE 65536
#define IMG_STRIDE 131072
#define LTHREADS 256
#define LBLOCKS (NPIX / LTHREADS)           // 4096, one pixel per thread
#define BTHREADS 256
#define BBLOCKS 256                         // one block per 16x16 supercell
#define FIXSCALE 1048576.0                  // 2^20

__device__ uint2              g_lut[NCELLS];
__device__ float4             g_cdata[NCELLS * CAPI];   // padded candidates
__device__ float4             g_ctr[K_REAL];            // (2ca,2cb,-|c|^2,w)
__device__ unsigned long long g_acc;                    // zero-init; self-reset
__device__ unsigned int       g_tickets;                // zero-init; wraps

// ---------------------------------------------------------------------------
// Build: block = supercell (16x16 cells), thread = cell.
// score s_k(x) = 2*c_k.x - |c_k|^2 ;  d^2(x,c_k) = |x|^2 - s_k(x).
// ---------------------------------------------------------------------------
__global__ __launch_bounds__(BTHREADS)
void build_kernel(const float* __restrict__ centers,
                  const float* __restrict__ cw) {
    __shared__ float4 sB[K_REAL];
    __shared__ float4 scand[SCAP];
    __shared__ float  swarp[BTHREADS / 32];
    __shared__ float  s_sth;
    __shared__ int    s_cnt;

    const int t = threadIdx.x;
    for (int i = t; i < K_REAL; i += BTHREADS) {
        float ca = centers[2 * i];
        float cb = centers[2 * i + 1];
        float4 v = make_float4(2.f * ca, 2.f * cb,
                               -(ca * ca + cb * cb), cw[i]);
        sB[i] = v;
        if (blockIdx.x == 0) g_ctr[i] = v;
    }
    __syncthreads();

    const int sx = blockIdx.x & 15;
    const int sy = blockIdx.x >> 4;
    const float sccx = 16.f * sx - 120.f;
    const float sccy = 16.f * sy - 120.f;
    const float scc2 = sccx * sccx + sccy * sccy;

    float m = -1e30f;
    for (int i = t; i < K_REAL; i += BTHREADS) {
        float4 c = sB[i];
        m = fmaxf(m, fmaf(c.x, sccx, fmaf(c.y, sccy, c.z)));
    }
    #pragma unroll
    for (int off = 16; off; off >>= 1)
        m = fmaxf(m, __shfl_xor_sync(0xFFFFFFFFu, m, off));
    if ((t & 31) == 0) swarp[t >> 5] = m;
    __syncthreads();
    if (t == 0) {
        float mm = swarp[0];
        #pragma unroll
        for (int wnum = 1; wnum < BTHREADS / 32; wnum++)
            mm = fmaxf(mm, swarp[wnum]);
        float d2min = fmaxf(scc2 - mm, 0.f);
        float T = sqrtf(d2min) + 22.75f;   // 2*7.5*sqrt2 + sqrt2 + margin
        s_sth = scc2 - T * T;
    }
    __syncthreads();

    // deterministic candidate compaction: warp 0 only, index-ordered
    if (t < 32) {
        const float sth_sc = s_sth;
        int cnt = 0;
        for (int base = 0; base < K_REAL; base += 32) {
            const int i = base + t;
            bool pred = false;
            float4 c = make_float4(0.f, 0.f, 0.f, 0.f);
            if (i < K_REAL) {
                c = sB[i];
                pred = (fmaf(c.x, sccx, fmaf(c.y, sccy, c.z)) >= sth_sc);
            }
            const unsigned mask = __ballot_sync(0xFFFFFFFFu, pred);
            if (pred) {
                const int pos = cnt + __popc(mask & ((1u << t) - 1u));
                if (pos < SCAP) scand[pos] = c;
            }
            cnt += __popc(mask);
        }
        if (t == 0) s_cnt = cnt;
    }
    __syncthreads();

    const float4* list;
    int n;
    if (s_cnt <= SCAP) { list = scand; n = s_cnt; }
    else               { list = sB;    n = K_REAL; }   // overflow fallback

    const int ix = 16 * sx + (t & 15);
    const int iy = 16 * sy + (t >> 4);
    const float ccx = (float)ix - 127.5f;
    const float ccy = (float)iy - 127.5f;
    const float cc2 = ccx * ccx + ccy * ccy;

    float smax = -1e30f;
    for (int k = 0; k < n; k++) {
        float4 c = list[k];
        smax = fmaxf(smax, fmaf(c.x, ccx, fmaf(c.y, ccy, c.z)));
    }
    float d2min = fmaxf(cc2 - smax, 0.f);
    float T = sqrtf(d2min) + 1.43421356f;  // sqrt(2) diag + fp margin
    const float sth = cc2 - T * T;

    const int cell = (iy << 8) | ix;
    int cnt = 0;
    float w0 = 0.f;
    float4* slot = &g_cdata[cell * CAPI];
    for (int k = 0; k < n; k++) {
        float4 c = list[k];
        float s = fmaf(c.x, ccx, fmaf(c.y, ccy, c.z));
        if (s >= sth) {
            if (cnt < CAPI) slot[cnt] = c;
            if (cnt == 0) w0 = c.w;
            cnt++;
        }
    }
    uint2 e;
    if (cnt == 1) {
        e.x = __float_as_uint(w0); e.y = 1u;
    } else if (cnt <= CAPI) {
        // pad remaining slots with sentinels so loss loads unconditionally
        const float4 sentinel = make_float4(0.f, 0.f, -1e30f, 0.f);
        for (int j = cnt; j < CAPI; j++) slot[j] = sentinel;
        e.x = 0u; e.y = (unsigned)cnt;
    } else {
        e.x = 0u; e.y = 0xFFFFu;               // loss full-scan fallback
    }
    g_lut[cell] = e;
}

// ---------------------------------------------------------------------------
// Loss: one pixel per thread; minimal chain depth, batched unguarded loads.
// ---------------------------------------------------------------------------
__global__ __launch_bounds__(LTHREADS)
void loss_kernel(const float* __restrict__ pred,
                 const float* __restrict__ target,
                 float* __restrict__ out) {
    __shared__ float sred[LTHREADS / 32];

    const int t = threadIdx.x;
    const int p = blockIdx.x * LTHREADS + t;   // pixel index
    const int b = p >> 16;
    const int r = p & 65535;

    const float* tb = target + (size_t)b * IMG_STRIDE + r;
    const float* pb = pred   + (size_t)b * IMG_STRIDE + r;
    const float f0 = __ldg(tb);
    const float f1 = __ldg(tb + CH_STRIDE);
    const float q0 = __ldg(pb);                // hoisted: overlap with LUT trip
    const float q1 = __ldg(pb + CH_STRIDE);

    const float xa = f0 * 128.f;
    const float xb = f1 * 128.f;
    int ix = __float2int_rd(xa + 128.f);
    int iy = __float2int_rd(xb + 128.f);
    ix = min(max(ix, 0), GRIDW - 1);
    iy = min(max(iy, 0), GRIDW - 1);
    const int cell = (iy << 8) | ix;
    const uint2 e = __ldg(&g_lut[cell]);
    const unsigned cnt = e.y;

    float w;
    if (cnt == 1u) {
        w = __uint_as_float(e.x);
    } else if (cnt <= (unsigned)CAPI) {
        const float4* cd = &g_cdata[cell * CAPI];
        // batch 1: four unconditional back-to-back loads (full MLP)
        float4 c0 = __ldg(cd + 0);
        float4 c1 = __ldg(cd + 1);
        float4 c2 = __ldg(cd + 2);
        float4 c3 = __ldg(cd + 3);
        float s0 = fmaf(c0.x, xa, fmaf(c0.y, xb, c0.z));
        float s1 = fmaf(c1.x, xa, fmaf(c1.y, xb, c1.z));
        float s2 = fmaf(c2.x, xa, fmaf(c2.y, xb, c2.z));
        float s3 = fmaf(c3.x, xa, fmaf(c3.y, xb, c3.z));
        float bs = s0, bw = c0.w;
        if (s1 > bs) { bs = s1; bw = c1.w; }
        if (s2 > bs) { bs = s2; bw = c2.w; }
        if (s3 > bs) { bs = s3; bw = c3.w; }
        if (cnt > 4u) {
            // batch 2: four more unconditional loads
            float4 c4 = __ldg(cd + 4);
            float4 c5 = __ldg(cd + 5);
            float4 c6 = __ldg(cd + 6);
            float4 c7 = __ldg(cd + 7);
            float s4 = fmaf(c4.x, xa, fmaf(c4.y, xb, c4.z));
            float s5 = fmaf(c5.x, xa, fmaf(c5.y, xb, c5.z));
            float s6 = fmaf(c6.x, xa, fmaf(c6.y, xb, c6.z));
            float s7 = fmaf(c7.x, xa, fmaf(c7.y, xb, c7.z));
            if (s4 > bs) { bs = s4; bw = c4.w; }
            if (s5 > bs) { bs = s5; bw = c5.w; }
            if (s6 > bs) { bs = s6; bw = c6.w; }
            if (s7 > bs) { bs = s7; bw = c7.w; }
        }
        w = bw;
    } else {   // pathological: exact full scan from L2
        float bs = -1e30f, bw = 0.f;
        for (int k = 0; k < K_REAL; k++) {
            float4 c = __ldg(&g_ctr[k]);
            float s = fmaf(c.x, xa, fmaf(c.y, xb, c.z));
            if (s > bs) { bs = s; bw = c.w; }
        }
        w = bw;
    }

    const float d0 = q0 - f0;
    const float d1 = q1 - f1;
    float acc = fmaf(d0, d0, d1 * d1) * w;

    // deterministic reduction: warp -> block -> fixed-point u64 atomic
    #pragma unroll
    for (int off = 16; off; off >>= 1)
        acc += __shfl_down_sync(0xFFFFFFFFu, acc, off);
    if ((t & 31) == 0) sred[t >> 5] = acc;
    __syncthreads();
    if (t < LTHREADS / 32) {
        float v = sred[t];
        #pragma unroll
        for (int off = (LTHREADS / 64); off; off >>= 1)
            v += __shfl_down_sync(0xFFu, v, off);
        if (t == 0) {
            const unsigned long long fx =
                (unsigned long long)__double2ll_rn((double)v * FIXSCALE);
            atomicAdd(&g_acc, fx);
            __threadfence();
            const unsigned ticket = atomicInc(&g_tickets, LBLOCKS - 1);
            if (ticket == LBLOCKS - 1) {
                const unsigned long long total = atomicAdd(&g_acc, 0ULL);
                out[0] = (float)((double)total * (1.0 / FIXSCALE / (double)NPIX));
                __threadfence();
                g_acc = 0ULL;                  // reset for next graph replay
            }
        }
    }
}

extern "C" void kernel_launch(void* const* d_in, const int* in_sizes, int n_in,
                              void* d_out, int out_size) {
    const float* pred    = (const float*)d_in[0];
    const float* target  = (const float*)d_in[1];
    const float* centers = (const float*)d_in[2];
    const float* cw      = (const float*)d_in[3];

    build_kernel<<<BBLOCKS, BTHREADS>>>(centers, cw);
    loss_kernel<<<LBLOCKS, LTHREADS>>>(pred, target, (float*)d_out);
}